// round 14
// baseline (speedup 1.0000x reference)
#include <cuda_runtime.h>

// Problem constants
#define L_   12
#define B_   4
#define H_   12
#define S_   785          // seq incl. CLS
#define NP   784          // LayerNorm width
#define KS   588          // 1-based k-th smallest
#define LN_EPS 1e-5f

// Stage-1 tiling: fine-grained chunks, ~7.8 waves for smooth tail.
#define CH     4                   // row chunks per (b, l, h)
#define ROWS_PER_CHUNK 196         // 784 / CH
#define ACC    7                   // 196 = 7 * 28, no remainder
#define ITERS  (ROWS_PER_CHUNK / ACC)   // 28
#define NPART  (144 * CH)          // 576 partials per b

// Stage-2 tiling: block = 128 cols x 8 subgroups; grid (7, 8, 4) = 224 blocks.
#define CSEG   7                   // ceil(784 / 128)
#define KGA    8                   // outer k-groups (grid dimension)
#define PER_KGA (NPART / KGA)      // 72
#define KG2    8                   // inner subgroups per block
#define PER_KG2 (PER_KGA / KG2)    // 9
#define BLKS_PER_BATCH (CSEG * KGA)   // 56

// Deterministic scratch (device globals — no allocation in kernel_launch)
__device__ float g_part1[B_ * NPART * S_];   // ~7.2 MB
__device__ float g_part2[B_ * KGA * NP];     // ~100 KB
__device__ int   g_cnt[B_];                  // zero-initialized; reset each run

// ---------------------------------------------------------------------------
// Kernel 1: streaming column sums (converged: ~80-82% DRAM, noise-bound).
// Block = (chunk, lh, b). Thread tid owns column tid (0..784); sums 196 rows
// with 7 independent accumulators. Warp LDG.32 covers 128 contiguous bytes.
// ---------------------------------------------------------------------------
__global__ __launch_bounds__(800, 2)
void colsum_kernel(const float* __restrict__ att) {
    const int tid   = threadIdx.x;
    if (tid >= S_) return;
    const int chunk = blockIdx.x;     // 0..CH-1
    const int lh    = blockIdx.y;     // 0..143
    const int b     = blockIdx.z;     // 0..3

    const int l = lh / H_;
    const int h = lh - l * H_;
    const int i0 = 1 + chunk * ROWS_PER_CHUNK;   // skip CLS row (i = 0)

    const size_t base =
        ((((size_t)l * B_ + b) * H_ + h) * S_ + i0) * (size_t)S_ + tid;
    const float* __restrict__ p = att + base;

    float a0 = 0.f, a1 = 0.f, a2 = 0.f, a3 = 0.f;
    float a4 = 0.f, a5 = 0.f, a6 = 0.f;

    #pragma unroll 1
    for (int r = 0; r < ITERS; ++r) {
        a0 += p[0 * S_];
        a1 += p[1 * S_];
        a2 += p[2 * S_];
        a3 += p[3 * S_];
        a4 += p[4 * S_];
        a5 += p[5 * S_];
        a6 += p[6 * S_];
        p += ACC * S_;
    }
    // fixed pairwise tree (deterministic)
    const float sum = ((a0 + a1) + (a2 + a3)) + ((a4 + a5) + a6);

    g_part1[((size_t)b * NPART + (size_t)lh * CH + chunk) * S_ + tid] = sum;
}

// ---------------------------------------------------------------------------
// Kernel 2 (fused): collapse 576 partials -> 8 per (b,col), then the LAST
// block of each batch (int-atomic ticket) runs the full finalize for that
// batch: sum 8 stage-2 partials, /144, LayerNorm, kthvalue threshold via
// 4-round 8-bit radix select on the monotone uint key (exact k-th value,
// ties as in sorting), mask in key domain. All summation orders fixed ->
// bitwise deterministic regardless of which block finishes last.
// ---------------------------------------------------------------------------
__global__ __launch_bounds__(1024, 2)
void reduce2_fin_kernel(const float* __restrict__ gamma,
                        const float* __restrict__ beta,
                        float* __restrict__ out) {
    __shared__ float sm[KG2][128];
    __shared__ float red[1024];
    __shared__ unsigned skey[NP];
    __shared__ int hist[256];
    __shared__ float s_mu, s_rstd;
    __shared__ unsigned s_prefix;
    __shared__ int s_k;
    __shared__ int s_last;

    const int tid  = threadIdx.x;
    const int lane = tid & 127;                   // column within segment
    const int kg2  = tid >> 7;                    // 0..7
    const int col  = blockIdx.x * 128 + lane;     // 0..895 (guard < 784)
    const int kgA  = blockIdx.y;                  // 0..7
    const int b    = blockIdx.z;

    // ---- stage 2: partial collapse (coalesced: 128 lanes read 512B runs) ----
    float s = 0.f;
    if (col < NP) {
        // output column col = source column (col + 1)  (skip CLS)
        const float* __restrict__ src = g_part1 +
            ((size_t)b * NPART + (size_t)kgA * PER_KGA + (size_t)kg2 * PER_KG2) * S_
            + (col + 1);
        #pragma unroll
        for (int k = 0; k < PER_KG2; ++k) s += src[(size_t)k * S_];
    }
    sm[kg2][lane] = s;
    __syncthreads();

    if (kg2 == 0 && col < NP) {
        // fixed pairwise tree (deterministic)
        float t0 = sm[0][lane] + sm[1][lane];
        float t1 = sm[2][lane] + sm[3][lane];
        float t2 = sm[4][lane] + sm[5][lane];
        float t3 = sm[6][lane] + sm[7][lane];
        g_part2[((size_t)b * KGA + kgA) * NP + col] = (t0 + t1) + (t2 + t3);
    }

    // ---- last-block election (per batch) ----
    __threadfence();          // make this block's g_part2 writes device-visible
    __syncthreads();          // all fences done before the ticket
    if (tid == 0) {
        const int old = atomicAdd(&g_cnt[b], 1);
        s_last = (old == BLKS_PER_BATCH - 1);
    }
    __syncthreads();
    if (!s_last) return;

    // ---- finalize for batch b (runs in exactly one block per batch) ----
    const int t = tid;

    float sv = 0.f;
    if (t < NP) {
        const float* __restrict__ src = g_part2 + (size_t)b * KGA * NP + t;
        // __ldcg: bypass L1 (other blocks produced these lines)
        float p0 = __ldcg(src + 0 * NP), p1 = __ldcg(src + 1 * NP);
        float p2 = __ldcg(src + 2 * NP), p3 = __ldcg(src + 3 * NP);
        float p4 = __ldcg(src + 4 * NP), p5 = __ldcg(src + 5 * NP);
        float p6 = __ldcg(src + 6 * NP), p7 = __ldcg(src + 7 * NP);
        sv = (((p0 + p1) + (p2 + p3)) + ((p4 + p5) + (p6 + p7))) * (1.0f / (L_ * H_));
    }

    // mean
    red[t] = (t < NP) ? sv : 0.f;
    __syncthreads();
    for (int o = 512; o > 0; o >>= 1) {
        if (t < o) red[t] += red[t + o];
        __syncthreads();
    }
    if (t == 0) s_mu = red[0] / NP;
    __syncthreads();
    const float mu = s_mu;

    // variance
    const float d = (t < NP) ? (sv - mu) : 0.f;
    red[t] = d * d;
    __syncthreads();
    for (int o = 512; o > 0; o >>= 1) {
        if (t < o) red[t] += red[t + o];
        __syncthreads();
    }
    if (t == 0) {
        s_rstd = rsqrtf(red[0] / NP + LN_EPS);
        s_prefix = 0u;
        s_k = KS;
    }
    __syncthreads();

    // LN value -> monotone uint key
    unsigned mykey = 0u;
    if (t < NP) {
        const float v = d * s_rstd * gamma[t] + beta[t];
        unsigned u = __float_as_uint(v);
        u = (u & 0x80000000u) ? ~u : (u | 0x80000000u);
        skey[t] = u;
        mykey = u;
    }
    __syncthreads();

    // 4-round radix select (MSB first) for the KS-th smallest key
    #pragma unroll
    for (int r = 0; r < 4; ++r) {
        const int sh = 24 - 8 * r;

        if (t < 256) hist[t] = 0;
        __syncthreads();

        if (t < NP) {
            bool act = (r == 0) ||
                       ((mykey >> (sh + 8)) == (s_prefix >> (sh + 8)));
            if (act) atomicAdd(&hist[(mykey >> sh) & 0xFFu], 1);
        }
        __syncthreads();

        if (t < 32) {
            // lane t owns bins 8t..8t+7
            int c[8], lsum = 0;
            #pragma unroll
            for (int i = 0; i < 8; ++i) { c[i] = hist[t * 8 + i]; lsum += c[i]; }
            // inclusive warp scan of lane sums
            int incl = lsum;
            #pragma unroll
            for (int o = 1; o < 32; o <<= 1) {
                int n = __shfl_up_sync(0xFFFFFFFFu, incl, o);
                if (t >= o) incl += n;
            }
            const int excl = incl - lsum;
            const int kk = s_k;
            if (excl < kk && kk <= incl) {     // exactly one lane
                int run = excl, bin = 0, newk = 0;
                #pragma unroll
                for (int i = 0; i < 8; ++i) {
                    if (newk == 0 && run + c[i] >= kk) { bin = t * 8 + i; newk = kk - run; }
                    run += c[i];
                }
                s_prefix |= (unsigned)bin << sh;
                s_k = newk;
            }
        }
        __syncthreads();
    }

    if (t < NP)
        out[(size_t)b * NP + t] = (skey[t] > s_prefix) ? 1.0f : 0.0f;

    // reset ticket for the next graph replay (kernel boundary = full fence)
    if (t == 0) g_cnt[b] = 0;
}

// ---------------------------------------------------------------------------
extern "C" void kernel_launch(void* const* d_in, const int* in_sizes, int n_in,
                              void* d_out, int out_size) {
    const float* att   = (const float*)d_in[0];
    const float* gamma = (const float*)d_in[1];
    const float* beta  = (const float*)d_in[2];
    float* out = (float*)d_out;

    colsum_kernel<<<dim3(CH, 144, B_), 800>>>(att);
    reduce2_fin_kernel<<<dim3(CSEG, KGA, B_), 1024>>>(gamma, beta, out);
}

// round 15
// speedup vs baseline: 1.0221x; 1.0221x over previous
#include <cuda_runtime.h>

// Problem constants
#define L_   12
#define B_   4
#define H_   12
#define S_   785          // seq incl. CLS
#define NP   784          // LayerNorm width
#define KS   588          // 1-based k-th smallest
#define LN_EPS 1e-5f

// Stage-1 tiling (R7 known-good config)
#define CH     2                   // row chunks per (b, l, h)
#define ROWS_PER_CHUNK 392         // 784 / CH
#define NPART  (144 * CH)          // 288 partials per b

// Stage-2 tiling: grid (25 colsegs, 4 kgA, 4 b) = 400 blocks.
#define KGA    4                   // outer k-groups (grid dimension)
#define PER_KGA (NPART / KGA)      // 72
#define KG2    8                   // inner subgroups per block
#define PER_KG2 (PER_KGA / KG2)    // 9

// Deterministic scratch (device globals — no allocation in kernel_launch)
__device__ float g_part1[B_ * NPART * S_];   // ~3.6 MB
__device__ float g_part2[B_ * KGA * NP];     // ~50 KB

// ---------------------------------------------------------------------------
// Kernel 1: streaming column sums (the proven 221.6us R7 version, unchanged).
// Block = (chunk, lh, b). Thread tid owns column tid (0..784); sums 392 rows
// with 8 independent accumulators. Warp LDG.32 covers 128 contiguous bytes.
// ---------------------------------------------------------------------------
__global__ __launch_bounds__(800, 2)
void colsum_kernel(const float* __restrict__ att) {
    const int tid   = threadIdx.x;
    if (tid >= S_) return;
    const int chunk = blockIdx.x;     // 0..CH-1
    const int lh    = blockIdx.y;     // 0..143
    const int b     = blockIdx.z;     // 0..3

    const int l = lh / H_;
    const int h = lh - l * H_;
    const int i0 = 1 + chunk * ROWS_PER_CHUNK;   // skip CLS row (i = 0)

    const size_t base =
        ((((size_t)l * B_ + b) * H_ + h) * S_ + i0) * (size_t)S_ + tid;
    const float* __restrict__ p = att + base;

    float a0 = 0.f, a1 = 0.f, a2 = 0.f, a3 = 0.f;
    float a4 = 0.f, a5 = 0.f, a6 = 0.f, a7 = 0.f;

    #pragma unroll 1
    for (int r = 0; r < ROWS_PER_CHUNK / 8; ++r) {
        a0 += p[0 * S_];
        a1 += p[1 * S_];
        a2 += p[2 * S_];
        a3 += p[3 * S_];
        a4 += p[4 * S_];
        a5 += p[5 * S_];
        a6 += p[6 * S_];
        a7 += p[7 * S_];
        p += 8 * S_;
    }
    // fixed pairwise tree (deterministic)
    const float sum = ((a0 + a1) + (a2 + a3)) + ((a4 + a5) + (a6 + a7));

    g_part1[((size_t)b * NPART + (size_t)lh * CH + chunk) * S_ + tid] = sum;
}

// ---------------------------------------------------------------------------
// Kernel 2: collapse 288 partials -> 4 per (b, col). 400 blocks (latency
// fully hidden). Block (cs, kgA, b), 256 threads = 32 cols x 8 subgroups.
// Thread (kg2, lane) sums 9 partials; smem tree 8 -> 1. Fixed order.
// ---------------------------------------------------------------------------
__global__ __launch_bounds__(256, 8)
void reduce2_kernel() {
    __shared__ float sm[KG2][32];

    const int tid  = threadIdx.x;
    const int lane = tid & 31;
    const int kg2  = tid >> 5;                    // 0..7
    const int col  = blockIdx.x * 32 + lane;      // 0..799 (guard < 784)
    const int kgA  = blockIdx.y;                  // 0..3
    const int b    = blockIdx.z;

    float s = 0.f;
    if (col < NP) {
        // output column col = source column (col + 1)  (skip CLS)
        const float* __restrict__ src = g_part1 +
            ((size_t)b * NPART + (size_t)kgA * PER_KGA + (size_t)kg2 * PER_KG2) * S_
            + (col + 1);
        #pragma unroll
        for (int k = 0; k < PER_KG2; ++k) s += src[(size_t)k * S_];
    }
    sm[kg2][lane] = s;
    __syncthreads();

    if (kg2 == 0 && col < NP) {
        // fixed pairwise tree (deterministic)
        float t0 = sm[0][lane] + sm[1][lane];
        float t1 = sm[2][lane] + sm[3][lane];
        float t2 = sm[4][lane] + sm[5][lane];
        float t3 = sm[6][lane] + sm[7][lane];
        g_part2[((size_t)b * KGA + kgA) * NP + col] = (t0 + t1) + (t2 + t3);
    }
}

// ---------------------------------------------------------------------------
// Kernel 3: per-batch finalize. Sum 4 stage-2 partials (L2-hot, coalesced,
// fixed tree), /144, LayerNorm (warp-shuffle reductions, 2 syncs each),
// then kthvalue threshold via 4-round 8-bit radix select on the monotone
// uint key (exact k-th value, ties as in sorting), mask in key domain.
// ---------------------------------------------------------------------------
__global__ __launch_bounds__(1024, 1)
void finalize_kernel(const float* __restrict__ gamma,
                     const float* __restrict__ beta,
                     float* __restrict__ out) {
    __shared__ float wred[32];
    __shared__ unsigned skey[NP];
    __shared__ int hist[256];
    __shared__ float s_mu, s_rstd;
    __shared__ unsigned s_prefix;
    __shared__ int s_k;

    const int b    = blockIdx.x;
    const int t    = threadIdx.x;
    const int lane = t & 31;
    const int warp = t >> 5;          // 0..31

    float s = 0.f;
    if (t < NP) {
        const float* __restrict__ src = g_part2 + (size_t)b * KGA * NP + t;
        float p0 = src[0 * NP], p1 = src[1 * NP];
        float p2 = src[2 * NP], p3 = src[3 * NP];
        s = ((p0 + p1) + (p2 + p3)) * (1.0f / (L_ * H_));
    }

    // ---- mean: warp shuffle tree (fixed order), then warp-0 combine ----
    float v = (t < NP) ? s : 0.f;
    #pragma unroll
    for (int o = 16; o > 0; o >>= 1) v += __shfl_down_sync(0xFFFFFFFFu, v, o);
    if (lane == 0) wred[warp] = v;
    __syncthreads();
    if (warp == 0) {
        float w = wred[lane];
        #pragma unroll
        for (int o = 16; o > 0; o >>= 1) w += __shfl_down_sync(0xFFFFFFFFu, w, o);
        if (lane == 0) s_mu = w / NP;
    }
    __syncthreads();
    const float mu = s_mu;

    // ---- variance: same pattern ----
    const float d = (t < NP) ? (s - mu) : 0.f;
    v = d * d;
    #pragma unroll
    for (int o = 16; o > 0; o >>= 1) v += __shfl_down_sync(0xFFFFFFFFu, v, o);
    if (lane == 0) wred[warp] = v;
    __syncthreads();
    if (warp == 0) {
        float w = wred[lane];
        #pragma unroll
        for (int o = 16; o > 0; o >>= 1) w += __shfl_down_sync(0xFFFFFFFFu, w, o);
        if (lane == 0) {
            s_rstd = rsqrtf(w / NP + LN_EPS);
            s_prefix = 0u;
            s_k = KS;
        }
    }
    __syncthreads();

    // LN value -> monotone uint key
    unsigned mykey = 0u;
    if (t < NP) {
        const float val = d * s_rstd * gamma[t] + beta[t];
        unsigned u = __float_as_uint(val);
        u = (u & 0x80000000u) ? ~u : (u | 0x80000000u);
        skey[t] = u;
        mykey = u;
    }
    __syncthreads();

    // 4-round radix select (MSB first) for the KS-th smallest key
    #pragma unroll
    for (int r = 0; r < 4; ++r) {
        const int sh = 24 - 8 * r;

        if (t < 256) hist[t] = 0;
        __syncthreads();

        if (t < NP) {
            bool act = (r == 0) ||
                       ((mykey >> (sh + 8)) == (s_prefix >> (sh + 8)));
            if (act) atomicAdd(&hist[(mykey >> sh) & 0xFFu], 1);
        }
        __syncthreads();

        if (t < 32) {
            // lane t owns bins 8t..8t+7
            int c[8], lsum = 0;
            #pragma unroll
            for (int i = 0; i < 8; ++i) { c[i] = hist[t * 8 + i]; lsum += c[i]; }
            // inclusive warp scan of lane sums
            int incl = lsum;
            #pragma unroll
            for (int o = 1; o < 32; o <<= 1) {
                int n = __shfl_up_sync(0xFFFFFFFFu, incl, o);
                if (t >= o) incl += n;
            }
            const int excl = incl - lsum;
            const int kk = s_k;
            if (excl < kk && kk <= incl) {     // exactly one lane
                int run = excl, bin = 0, newk = 0;
                #pragma unroll
                for (int i = 0; i < 8; ++i) {
                    if (newk == 0 && run + c[i] >= kk) { bin = t * 8 + i; newk = kk - run; }
                    run += c[i];
                }
                s_prefix |= (unsigned)bin << sh;
                s_k = newk;
            }
        }
        __syncthreads();
    }

    if (t < NP)
        out[(size_t)b * NP + t] = (skey[t] > s_prefix) ? 1.0f : 0.0f;
}

// ---------------------------------------------------------------------------
extern "C" void kernel_launch(void* const* d_in, const int* in_sizes, int n_in,
                              void* d_out, int out_size) {
    const float* att   = (const float*)d_in[0];
    const float* gamma = (const float*)d_in[1];
    const float* beta  = (const float*)d_in[2];
    float* out = (float*)d_out;

    colsum_kernel<<<dim3(CH, 144, B_), 800>>>(att);
    reduce2_kernel<<<dim3(25, KGA, B_), 256>>>();
    finalize_kernel<<<B_, 1024>>>(gamma, beta, out);
}